// round 8
// baseline (speedup 1.0000x reference)
#include <cuda_runtime.h>
#include <cuda_pipeline.h>
#include <math.h>

#define T_STEPS 1440
#define SEG_LEN 32
#define NSEG    45           // 1440 / 32
#define B_MAX   16384
#define NTILES  (B_MAX / 32) // 512
#define WPB     2            // warps per block
#define CH      4            // timesteps per chunk
#define NCHUNK  (SEG_LEN / CH)  // 8
#define ROWSTRIDE_B 80       // 4 float4 + 16B pad -> conflict-free LDS.128

// Decoupled-lookback state. Separate partial/inclusive payload arrays so a
// flag upgrade (1 -> 2) can never produce a torn payload read.
__device__ float2 g_part[NSEG * B_MAX];
__device__ float2 g_incl[NSEG * B_MAX];
__device__ int    g_flag[NSEG * B_MAX];

struct Coefs { float k1, k2, k3, e1, e2, e3; };

__device__ __forceinline__ float bsig(float raw, float lo, float hi) {
    return lo + (hi - lo) / (1.0f + expf(-raw));
}

__device__ __forceinline__ Coefs get_coefs(
    const float* rRi, const float* rRe, const float* rCi, const float* rCe,
    const float* rAi, const float* rAe, const float* rHg)
{
    float Ri = bsig(rRi[0], 1e-4f, 0.2f);
    float Re = bsig(rRe[0], 1e-4f, 0.2f);
    float Ci = bsig(rCi[0], 1e5f,  1e8f);
    float Ce = bsig(rCe[0], 1e5f,  1e8f);
    float Ai = bsig(rAi[0], 0.0f,  0.2f);
    float Ae = bsig(rAe[0], 0.0f,  0.2f);
    float Hg = bsig(rHg[0], 1.0f,  2e4f);
    float dci = 300.0f / Ci;
    float dce = 300.0f / Ce;
    Coefs c;
    c.k1 = dci / Ri;  c.k2 = dci * Ai;  c.k3 = -dci * Hg;  // MODE_COOL
    c.e1 = dce / Ri;  c.e2 = dce / Re;  c.e3 = dce * Ae;
    return c;
}

// Warp-per-(32-building tile, 32-step segment); 2 warps/block for occupancy.
// cp.async 2-stage 4-step-chunk pipeline (2.5KB/buffer); in-register outputs
// + decoupled lookback correction; coalesced flush via XOR-swizzled transpose.
__global__ void __launch_bounds__(32 * WPB, 18) rc_lookback(
    const float4* __restrict__ in, float* __restrict__ out,
    const float* __restrict__ rRi, const float* __restrict__ rRe,
    const float* __restrict__ rCi, const float* __restrict__ rCe,
    const float* __restrict__ rAi, const float* __restrict__ rAe,
    const float* __restrict__ rHg, int B)
{
    // per warp: two 2.5KB chunk buffers (32 rows x 80B); reused afterwards as
    // the 32x32-float XOR-swizzled transpose stage (4KB <= 5KB).
    __shared__ __align__(16) char sbuf[WPB][2][32 * ROWSTRIDE_B];

    int w    = threadIdx.x >> 5;
    int lane = threadIdx.x & 31;

    int unit = blockIdx.x * WPB + w;     // monotone in s -> lookback progress
    int s    = unit / NTILES;
    int tl   = unit - s * NTILES;
    int b0   = tl * 32;
    int b    = b0 + lane;

    Coefs c = get_coefs(rRi, rRe, rCi, rCe, rAi, rAe, rHg);
    float a00 = 1.0f - c.k1, a01 = c.k1;
    float a10 = c.e1,        a11 = 1.0f - c.e1 - c.e2;

    const char* gbase = (const char*)(in + (size_t)b0 * T_STEPS + s * SEG_LEN);
    int jr = lane & 3;     // t-col within 4-step chunk
    int rr = lane >> 2;    // row-group: 4 lanes per row, 8 rows per instruction

    // issue chunk ch's 4 coalesced 16B async copies for this lane
    auto issue_chunk = [&](int ch) {
        char* buf = sbuf[w][ch & 1];
        #pragma unroll
        for (int i = 0; i < 4; i++) {
            int r = i * 8 + rr;
            const char* src = gbase + ((size_t)r * T_STEPS + ch * CH + jr) * 16;
            char* dst = buf + r * ROWSTRIDE_B + jr * 16;
            __pipeline_memcpy_async(dst, src, 16);
        }
        __pipeline_commit();
    };

    issue_chunk(0);
    issue_chunk(1);

    float outs[SEG_LEN];
    float pin = 0.0f, penv = 0.0f;
    bool first = (s == 0);

    #pragma unroll
    for (int ch = 0; ch < NCHUNK; ch++) {
        __pipeline_wait_prior(1);            // chunk ch resident
        __syncwarp();
        const float4* buf = reinterpret_cast<const float4*>(sbuf[w][ch & 1]);
        if (ch == 0 && first) {              // true initial condition
            float4 f0 = buf[lane * 5 + 0];
            pin  = f0.x;
            penv = 0.5f * (f0.x + f0.y);
        }
        #pragma unroll
        for (int j = 0; j < CH; j++) {
            float4 f = buf[lane * 5 + j];    // padded stride: conflict-free
            float t_out = f.y, hv = f.z, sol = f.w;
            float p    = fmaf(c.k2, sol, c.k3 * hv);
            float nin  = fmaf(c.k1, penv - pin, pin + p);
            float q    = fmaf(c.e3, sol, penv);
            float nenv = fmaf(c.e1, pin - penv, fmaf(c.e2, t_out - penv, q));
            pin = nin; penv = nenv;
            outs[ch * CH + j] = nin;
        }
        __syncwarp();
        if (ch + 2 < NCHUNK) issue_chunk(ch + 2); // refill freed buffer
        else                 __pipeline_commit(); // empty group: uniform count
    }

    int idx = s * B + b;
    float xi = 0.0f, xe = 0.0f;
    if (first) {
        g_incl[idx] = make_float2(pin, penv);
        __threadfence();
        *(volatile int*)&g_flag[idx] = 2;
    } else {
        g_part[idx] = make_float2(pin, penv);
        __threadfence();
        *(volatile int*)&g_flag[idx] = 1;

        // M = A^32 via 5 squarings
        float m00 = a00, m01 = a01, m10 = a10, m11 = a11;
        #pragma unroll
        for (int i = 0; i < 5; i++) {
            float tr  = m00 + m11;
            float n00 = fmaf(m00, m00, m01 * m10);
            float n11 = fmaf(m11, m11, m01 * m10);
            float n01 = m01 * tr;
            float n10 = m10 * tr;
            m00 = n00; m01 = n01; m10 = n10; m11 = n11;
        }

        // lookback: x_start = d_{s-1} + M d_{s-2} + ... + M^{s-1-i} incl_i
        float p00 = 1.0f, p01 = 0.0f, p10 = 0.0f, p11 = 1.0f;
        for (int i = s - 1; i >= 0; --i) {
            int pidx = i * B + b;
            int f;
            while ((f = *(volatile int*)&g_flag[pidx]) == 0) { __nanosleep(40); }
            __threadfence();
            const float* vp = (f == 2) ? (const float*)&g_incl[pidx]
                                       : (const float*)&g_part[pidx];
            float vx = *(volatile const float*)(vp + 0);
            float vy = *(volatile const float*)(vp + 1);
            xi = fmaf(p00, vx, fmaf(p01, vy, xi));
            xe = fmaf(p10, vx, fmaf(p11, vy, xe));
            if (f == 2) break;
            float q00 = fmaf(p00, m00, p01 * m10), q01 = fmaf(p00, m01, p01 * m11);
            float q10 = fmaf(p10, m00, p11 * m10), q11 = fmaf(p10, m01, p11 * m11);
            p00 = q00; p01 = q01; p10 = q10; p11 = q11;
        }

        // publish inclusive ASAP to unblock successors
        float ix = fmaf(m00, xi, fmaf(m01, xe, pin));
        float ie = fmaf(m10, xi, fmaf(m11, xe, penv));
        g_incl[idx] = make_float2(ix, ie);
        __threadfence();
        *(volatile int*)&g_flag[idx] = 2;

        // in-register correction: outs[j] += row0(A^{j+1}) . x_start
        float al = a00, be = a01;
        #pragma unroll
        for (int j = 0; j < SEG_LEN; j++) {
            outs[j] = fmaf(al, xi, fmaf(be, xe, outs[j]));
            float nal = fmaf(al, a00, be * a10);
            float nbe = fmaf(al, a01, be * a11);
            al = nal; be = nbe;
        }
    }

    // transpose through smem (reuse both chunk buffers), XOR-swizzled 32x32
    __syncwarp();
    float* ot = reinterpret_cast<float*>(&sbuf[w][0][0]);
    #pragma unroll
    for (int j = 0; j < SEG_LEN; j++)
        ot[lane * 32 + (j ^ lane)] = outs[j];          // banks distinct per j
    __syncwarp();
    float* obase = out + (size_t)b0 * T_STEPS + s * SEG_LEN;
    #pragma unroll
    for (int r = 0; r < 32; r++)
        __stcs(obase + (size_t)r * T_STEPS + lane, ot[r * 32 + (lane ^ r)]);
}

// ---------------------------------------------------------------------------
extern "C" void kernel_launch(void* const* d_in, const int* in_sizes, int n_in,
                              void* d_out, int out_size) {
    const float4* in  = (const float4*)d_in[0];
    const float* rRi = (const float*)d_in[1];
    const float* rRe = (const float*)d_in[2];
    const float* rCi = (const float*)d_in[3];
    const float* rCe = (const float*)d_in[4];
    const float* rAi = (const float*)d_in[5];
    const float* rAe = (const float*)d_in[6];
    const float* rHg = (const float*)d_in[7];
    float* out = (float*)d_out;

    int B = in_sizes[0] / (T_STEPS * 4);   // 16384

    // reset lookback flags (graph-capturable memset node; no allocation)
    void* flag_ptr = nullptr;
    cudaGetSymbolAddress(&flag_ptr, g_flag);
    cudaMemsetAsync(flag_ptr, 0, (size_t)NSEG * B_MAX * sizeof(int), 0);

    int units  = NTILES * NSEG;            // 23040
    int blocks = units / WPB;              // 11520
    rc_lookback<<<blocks, 32 * WPB>>>(in, out, rRi, rRe, rCi, rCe, rAi, rAe, rHg, B);
}

// round 9
// speedup vs baseline: 1.0619x; 1.0619x over previous
#include <cuda_runtime.h>
#include <cuda_pipeline.h>
#include <math.h>

#define T_STEPS 1440
#define SEG_LEN 32
#define NSEG    45           // 1440 / 32
#define B_MAX   16384
#define NSTAGE  3            // cp.async pipeline depth
#define NCHUNK  4            // 4 chunks x 8 steps = 32

// Decoupled-lookback state. Separate partial/inclusive payload arrays so a
// flag upgrade (1 -> 2) can never produce a torn payload read.
__device__ float2 g_part[NSEG * B_MAX];
__device__ float2 g_incl[NSEG * B_MAX];
__device__ int    g_flag[NSEG * B_MAX];

struct Coefs { float k1, k2, k3, e1, e2, e3; };

__device__ __forceinline__ float bsig(float raw, float lo, float hi) {
    return lo + (hi - lo) / (1.0f + expf(-raw));
}

__device__ __forceinline__ Coefs get_coefs(
    const float* rRi, const float* rRe, const float* rCi, const float* rCe,
    const float* rAi, const float* rAe, const float* rHg)
{
    float Ri = bsig(rRi[0], 1e-4f, 0.2f);
    float Re = bsig(rRe[0], 1e-4f, 0.2f);
    float Ci = bsig(rCi[0], 1e5f,  1e8f);
    float Ce = bsig(rCe[0], 1e5f,  1e8f);
    float Ai = bsig(rAi[0], 0.0f,  0.2f);
    float Ae = bsig(rAe[0], 0.0f,  0.2f);
    float Hg = bsig(rHg[0], 1.0f,  2e4f);
    float dci = 300.0f / Ci;
    float dce = 300.0f / Ce;
    Coefs c;
    c.k1 = dci / Ri;  c.k2 = dci * Ai;  c.k3 = -dci * Hg;  // MODE_COOL
    c.e1 = dce / Ri;  c.e2 = dce / Re;  c.e3 = dce * Ae;
    return c;
}

// One warp-block per (32-building tile, 32-step segment). 3-stage cp.async
// chunk pipeline (12KB outstanding at prolog); XOR-swizzled smem tiles;
// in-register outputs + lookback correction; coalesced transpose flush.
__global__ void __launch_bounds__(32) rc_lookback(
    const float4* __restrict__ in, float* __restrict__ out,
    const float* __restrict__ rRi, const float* __restrict__ rRe,
    const float* __restrict__ rCi, const float* __restrict__ rCe,
    const float* __restrict__ rAi, const float* __restrict__ rAe,
    const float* __restrict__ rHg, int B)
{
    // three 4KB chunk buffers (32 rows x 8 float4, XOR swizzled);
    // first two reused as the 32x33-float output transpose stage afterwards.
    __shared__ __align__(16) char sbuf[NSTAGE][32 * 8 * 16];

    int lane = threadIdx.x;
    int s    = blockIdx.y;
    int b0   = blockIdx.x * 32;
    int b    = b0 + lane;

    Coefs c = get_coefs(rRi, rRe, rCi, rCe, rAi, rAe, rHg);
    float a00 = 1.0f - c.k1, a01 = c.k1;
    float a10 = c.e1,        a11 = 1.0f - c.e1 - c.e2;

    const char* gbase = (const char*)(in + (size_t)b0 * T_STEPS + s * SEG_LEN);
    int jr = lane & 7;     // t-col within 8-step chunk (load phase)
    int rr = lane >> 3;    // row-group (load phase): 8 lanes per row

    // issue chunk ch's 8 coalesced 16B async copies for this lane
    auto issue_chunk = [&](int ch) {
        char* buf = sbuf[ch % NSTAGE];
        #pragma unroll
        for (int i = 0; i < 8; i++) {
            int r = i * 4 + rr;
            const char* src = gbase + ((size_t)r * T_STEPS + ch * 8 + jr) * 16;
            char* dst = buf + r * 128 + ((jr ^ (r & 7)) * 16);
            __pipeline_memcpy_async(dst, src, 16);
        }
        __pipeline_commit();
    };

    // prolog: 3 of 4 chunks in flight (12KB outstanding per warp)
    issue_chunk(0);
    issue_chunk(1);
    issue_chunk(2);

    float outs[SEG_LEN];
    float pin = 0.0f, penv = 0.0f;
    bool first = (s == 0);

    #pragma unroll
    for (int ch = 0; ch < NCHUNK; ch++) {
        __pipeline_wait_prior(NSTAGE - 1);   // chunk ch resident
        __syncwarp();
        const float4* buf = reinterpret_cast<const float4*>(sbuf[ch % NSTAGE]);
        if (ch == 0 && first) {              // true initial condition
            float4 f0 = buf[lane * 8 + (0 ^ (lane & 7))];
            pin  = f0.x;
            penv = 0.5f * (f0.x + f0.y);
        }
        #pragma unroll
        for (int j = 0; j < 8; j++) {
            float4 f = buf[lane * 8 + (j ^ (lane & 7))];   // conflict-free
            float t_out = f.y, hv = f.z, sol = f.w;
            float p    = fmaf(c.k2, sol, c.k3 * hv);
            float nin  = fmaf(c.k1, penv - pin, pin + p);
            float q    = fmaf(c.e3, sol, penv);
            float nenv = fmaf(c.e1, pin - penv, fmaf(c.e2, t_out - penv, q));
            pin = nin; penv = nenv;
            outs[ch * 8 + j] = nin;
        }
        __syncwarp();
        if (ch + NSTAGE < NCHUNK) issue_chunk(ch + NSTAGE); // refill freed buffer
        else                      __pipeline_commit();      // empty: uniform count
    }

    int idx = s * B + b;
    float xi = 0.0f, xe = 0.0f;
    if (first) {
        g_incl[idx] = make_float2(pin, penv);
        __threadfence();
        *(volatile int*)&g_flag[idx] = 2;
    } else {
        g_part[idx] = make_float2(pin, penv);
        __threadfence();
        *(volatile int*)&g_flag[idx] = 1;

        // M = A^32 via 5 squarings
        float m00 = a00, m01 = a01, m10 = a10, m11 = a11;
        #pragma unroll
        for (int i = 0; i < 5; i++) {
            float tr  = m00 + m11;
            float n00 = fmaf(m00, m00, m01 * m10);
            float n11 = fmaf(m11, m11, m01 * m10);
            float n01 = m01 * tr;
            float n10 = m10 * tr;
            m00 = n00; m01 = n01; m10 = n10; m11 = n11;
        }

        // lookback: x_start = d_{s-1} + M d_{s-2} + ... + M^{s-1-i} incl_i
        float p00 = 1.0f, p01 = 0.0f, p10 = 0.0f, p11 = 1.0f;
        for (int i = s - 1; i >= 0; --i) {
            int pidx = i * B + b;
            int f;
            while ((f = *(volatile int*)&g_flag[pidx]) == 0) { __nanosleep(40); }
            __threadfence();
            const float* vp = (f == 2) ? (const float*)&g_incl[pidx]
                                       : (const float*)&g_part[pidx];
            float vx = *(volatile const float*)(vp + 0);
            float vy = *(volatile const float*)(vp + 1);
            xi = fmaf(p00, vx, fmaf(p01, vy, xi));
            xe = fmaf(p10, vx, fmaf(p11, vy, xe));
            if (f == 2) break;
            float q00 = fmaf(p00, m00, p01 * m10), q01 = fmaf(p00, m01, p01 * m11);
            float q10 = fmaf(p10, m00, p11 * m10), q11 = fmaf(p10, m01, p11 * m11);
            p00 = q00; p01 = q01; p10 = q10; p11 = q11;
        }

        // publish inclusive ASAP to unblock successors
        float ix = fmaf(m00, xi, fmaf(m01, xe, pin));
        float ie = fmaf(m10, xi, fmaf(m11, xe, penv));
        g_incl[idx] = make_float2(ix, ie);
        __threadfence();
        *(volatile int*)&g_flag[idx] = 2;

        // in-register correction: outs[j] += row0(A^{j+1}) . x_start
        float al = a00, be = a01;
        #pragma unroll
        for (int j = 0; j < SEG_LEN; j++) {
            outs[j] = fmaf(al, xi, fmaf(be, xe, outs[j]));
            float nal = fmaf(al, a00, be * a10);
            float nbe = fmaf(al, a01, be * a11);
            al = nal; be = nbe;
        }
    }

    // transpose through smem (reuse chunk buffers; 4224B spans buf0+buf1),
    // coalesced 128B row stores, streaming hint
    __syncwarp();
    float* ot = reinterpret_cast<float*>(&sbuf[0][0]);
    #pragma unroll
    for (int j = 0; j < SEG_LEN; j++) ot[lane * 33 + j] = outs[j];  // stride 33: conflict-free
    __syncwarp();
    float* obase = out + (size_t)b0 * T_STEPS + s * SEG_LEN;
    #pragma unroll
    for (int r = 0; r < 32; r++)
        __stcs(obase + (size_t)r * T_STEPS + lane, ot[r * 33 + lane]);
}

// ---------------------------------------------------------------------------
extern "C" void kernel_launch(void* const* d_in, const int* in_sizes, int n_in,
                              void* d_out, int out_size) {
    const float4* in  = (const float4*)d_in[0];
    const float* rRi = (const float*)d_in[1];
    const float* rRe = (const float*)d_in[2];
    const float* rCi = (const float*)d_in[3];
    const float* rCe = (const float*)d_in[4];
    const float* rAi = (const float*)d_in[5];
    const float* rAe = (const float*)d_in[6];
    const float* rHg = (const float*)d_in[7];
    float* out = (float*)d_out;

    int B = in_sizes[0] / (T_STEPS * 4);   // 16384

    // reset lookback flags (graph-capturable memset node; no allocation)
    void* flag_ptr = nullptr;
    cudaGetSymbolAddress(&flag_ptr, g_flag);
    cudaMemsetAsync(flag_ptr, 0, (size_t)NSEG * B_MAX * sizeof(int), 0);

    dim3 grid(B / 32, NSEG);
    rc_lookback<<<grid, 32>>>(in, out, rRi, rRe, rCi, rCe, rAi, rAe, rHg, B);
}

// round 10
// speedup vs baseline: 1.1127x; 1.0478x over previous
#include <cuda_runtime.h>
#include <cuda_pipeline.h>
#include <math.h>

#define T_STEPS 1440
#define SEG_LEN 32
#define NSEG    45           // 1440 / 32
#define B_MAX   16384
#define NTILES  (B_MAX / 32) // 512
#define WPB     2            // warps per block

// Decoupled-lookback state. Separate partial/inclusive payload arrays so a
// flag upgrade (1 -> 2) can never produce a torn payload read.
__device__ float2 g_part[NSEG * B_MAX];
__device__ float2 g_incl[NSEG * B_MAX];
__device__ int    g_flag[NSEG * B_MAX];

struct Coefs { float k1, k2, k3, e1, e2, e3; };

__device__ __forceinline__ float bsig(float raw, float lo, float hi) {
    return lo + (hi - lo) / (1.0f + expf(-raw));
}

__device__ __forceinline__ Coefs get_coefs(
    const float* rRi, const float* rRe, const float* rCi, const float* rCe,
    const float* rAi, const float* rAe, const float* rHg)
{
    float Ri = bsig(rRi[0], 1e-4f, 0.2f);
    float Re = bsig(rRe[0], 1e-4f, 0.2f);
    float Ci = bsig(rCi[0], 1e5f,  1e8f);
    float Ce = bsig(rCe[0], 1e5f,  1e8f);
    float Ai = bsig(rAi[0], 0.0f,  0.2f);
    float Ae = bsig(rAe[0], 0.0f,  0.2f);
    float Hg = bsig(rHg[0], 1.0f,  2e4f);
    float dci = 300.0f / Ci;
    float dce = 300.0f / Ce;
    Coefs c;
    c.k1 = dci / Ri;  c.k2 = dci * Ai;  c.k3 = -dci * Hg;  // MODE_COOL
    c.e1 = dce / Ri;  c.e2 = dce / Re;  c.e3 = dce * Ae;
    return c;
}

// Warp-per-(32-building tile, 32-step segment), 2 warps/block. Per-warp
// 2-stage cp.async chunk pipeline (8KB); XOR-swizzled smem tiles; in-register
// outputs + decoupled-lookback correction; coalesced transpose flush.
// No max-blocks clause: let ptxas pick registers freely (R7's cap caused spills).
__global__ void __launch_bounds__(32 * WPB) rc_lookback(
    const float4* __restrict__ in, float* __restrict__ out,
    const float* __restrict__ rRi, const float* __restrict__ rRe,
    const float* __restrict__ rCi, const float* __restrict__ rCe,
    const float* __restrict__ rAi, const float* __restrict__ rAe,
    const float* __restrict__ rHg, int B)
{
    // per warp: two 4KB chunk buffers (32 rows x 8 float4, XOR swizzled);
    // reused afterwards as the 32x33-float output transpose stage.
    __shared__ __align__(16) char sbuf[WPB][2][32 * 8 * 16];

    int w    = threadIdx.x >> 5;
    int lane = threadIdx.x & 31;

    int unit = blockIdx.x * WPB + w;     // monotone in s -> lookback progress
    int s    = unit / NTILES;
    int tl   = unit - s * NTILES;
    int b0   = tl * 32;
    int b    = b0 + lane;

    Coefs c = get_coefs(rRi, rRe, rCi, rCe, rAi, rAe, rHg);
    float a00 = 1.0f - c.k1, a01 = c.k1;
    float a10 = c.e1,        a11 = 1.0f - c.e1 - c.e2;

    const char* gbase = (const char*)(in + (size_t)b0 * T_STEPS + s * SEG_LEN);
    int jr = lane & 7;     // t-col within 8-step chunk (load phase)
    int rr = lane >> 3;    // row-group (load phase): 8 lanes per row

    // issue chunk ch's 8 coalesced 16B async copies for this lane
    auto issue_chunk = [&](int ch) {
        char* buf = sbuf[w][ch & 1];
        #pragma unroll
        for (int i = 0; i < 8; i++) {
            int r = i * 4 + rr;
            const char* src = gbase + ((size_t)r * T_STEPS + ch * 8 + jr) * 16;
            char* dst = buf + r * 128 + ((jr ^ (r & 7)) * 16);
            __pipeline_memcpy_async(dst, src, 16);
        }
        __pipeline_commit();
    };

    issue_chunk(0);
    issue_chunk(1);

    float outs[SEG_LEN];
    float pin = 0.0f, penv = 0.0f;
    bool first = (s == 0);

    #pragma unroll
    for (int ch = 0; ch < 4; ch++) {
        __pipeline_wait_prior(1);            // chunk ch resident
        __syncwarp();
        const float4* buf = reinterpret_cast<const float4*>(sbuf[w][ch & 1]);
        if (ch == 0 && first) {              // true initial condition
            float4 f0 = buf[lane * 8 + (0 ^ (lane & 7))];
            pin  = f0.x;
            penv = 0.5f * (f0.x + f0.y);
        }
        #pragma unroll
        for (int j = 0; j < 8; j++) {
            float4 f = buf[lane * 8 + (j ^ (lane & 7))];   // conflict-free
            float t_out = f.y, hv = f.z, sol = f.w;
            float p    = fmaf(c.k2, sol, c.k3 * hv);
            float nin  = fmaf(c.k1, penv - pin, pin + p);
            float q    = fmaf(c.e3, sol, penv);
            float nenv = fmaf(c.e1, pin - penv, fmaf(c.e2, t_out - penv, q));
            pin = nin; penv = nenv;
            outs[ch * 8 + j] = nin;
        }
        __syncwarp();
        if (ch + 2 < 4) issue_chunk(ch + 2);  // refill the buffer just freed
        else            __pipeline_commit();  // empty group: uniform count
    }

    int idx = s * B + b;
    float xi = 0.0f, xe = 0.0f;
    if (first) {
        g_incl[idx] = make_float2(pin, penv);
        __threadfence();
        *(volatile int*)&g_flag[idx] = 2;
    } else {
        g_part[idx] = make_float2(pin, penv);
        __threadfence();
        *(volatile int*)&g_flag[idx] = 1;

        // M = A^32 via 5 squarings
        float m00 = a00, m01 = a01, m10 = a10, m11 = a11;
        #pragma unroll
        for (int i = 0; i < 5; i++) {
            float tr  = m00 + m11;
            float n00 = fmaf(m00, m00, m01 * m10);
            float n11 = fmaf(m11, m11, m01 * m10);
            float n01 = m01 * tr;
            float n10 = m10 * tr;
            m00 = n00; m01 = n01; m10 = n10; m11 = n11;
        }

        // lookback: x_start = d_{s-1} + M d_{s-2} + ... + M^{s-1-i} incl_i
        float p00 = 1.0f, p01 = 0.0f, p10 = 0.0f, p11 = 1.0f;
        for (int i = s - 1; i >= 0; --i) {
            int pidx = i * B + b;
            int f;
            while ((f = *(volatile int*)&g_flag[pidx]) == 0) { __nanosleep(40); }
            __threadfence();
            const float* vp = (f == 2) ? (const float*)&g_incl[pidx]
                                       : (const float*)&g_part[pidx];
            float vx = *(volatile const float*)(vp + 0);
            float vy = *(volatile const float*)(vp + 1);
            xi = fmaf(p00, vx, fmaf(p01, vy, xi));
            xe = fmaf(p10, vx, fmaf(p11, vy, xe));
            if (f == 2) break;
            float q00 = fmaf(p00, m00, p01 * m10), q01 = fmaf(p00, m01, p01 * m11);
            float q10 = fmaf(p10, m00, p11 * m10), q11 = fmaf(p10, m01, p11 * m11);
            p00 = q00; p01 = q01; p10 = q10; p11 = q11;
        }

        // publish inclusive ASAP to unblock successors
        float ix = fmaf(m00, xi, fmaf(m01, xe, pin));
        float ie = fmaf(m10, xi, fmaf(m11, xe, penv));
        g_incl[idx] = make_float2(ix, ie);
        __threadfence();
        *(volatile int*)&g_flag[idx] = 2;

        // in-register correction: outs[j] += row0(A^{j+1}) . x_start
        float al = a00, be = a01;
        #pragma unroll
        for (int j = 0; j < SEG_LEN; j++) {
            outs[j] = fmaf(al, xi, fmaf(be, xe, outs[j]));
            float nal = fmaf(al, a00, be * a10);
            float nbe = fmaf(al, a01, be * a11);
            al = nal; be = nbe;
        }
    }

    // transpose through this warp's smem (4224B spans its two 4KB buffers),
    // coalesced 128B row stores with streaming hint
    __syncwarp();
    float* ot = reinterpret_cast<float*>(&sbuf[w][0][0]);
    #pragma unroll
    for (int j = 0; j < SEG_LEN; j++) ot[lane * 33 + j] = outs[j];  // stride 33: conflict-free
    __syncwarp();
    float* obase = out + (size_t)b0 * T_STEPS + s * SEG_LEN;
    #pragma unroll
    for (int r = 0; r < 32; r++)
        __stcs(obase + (size_t)r * T_STEPS + lane, ot[r * 33 + lane]);
}

// ---------------------------------------------------------------------------
extern "C" void kernel_launch(void* const* d_in, const int* in_sizes, int n_in,
                              void* d_out, int out_size) {
    const float4* in  = (const float4*)d_in[0];
    const float* rRi = (const float*)d_in[1];
    const float* rRe = (const float*)d_in[2];
    const float* rCi = (const float*)d_in[3];
    const float* rCe = (const float*)d_in[4];
    const float* rAi = (const float*)d_in[5];
    const float* rAe = (const float*)d_in[6];
    const float* rHg = (const float*)d_in[7];
    float* out = (float*)d_out;

    int B = in_sizes[0] / (T_STEPS * 4);   // 16384

    // reset lookback flags (graph-capturable memset node; no allocation)
    void* flag_ptr = nullptr;
    cudaGetSymbolAddress(&flag_ptr, g_flag);
    cudaMemsetAsync(flag_ptr, 0, (size_t)NSEG * B_MAX * sizeof(int), 0);

    int units  = NTILES * NSEG;            // 23040
    int blocks = units / WPB;              // 11520
    rc_lookback<<<blocks, 32 * WPB>>>(in, out, rRi, rRe, rCi, rCe, rAi, rAe, rHg, B);
}

// round 11
// speedup vs baseline: 1.1374x; 1.0222x over previous
#include <cuda_runtime.h>
#include <cuda_pipeline.h>
#include <math.h>

#define T_STEPS 1440
#define SEG_LEN 32
#define NSEG    45           // 1440 / 32
#define B_MAX   16384
#define NTILES  (B_MAX / 32) // 512
#define WPB     2            // warps per block

// Decoupled-lookback state with epoch-tagged flags (no per-launch memset).
__device__ float2 g_part[NSEG * B_MAX];
__device__ float2 g_incl[NSEG * B_MAX];
__device__ int    g_flag[NSEG * B_MAX];   // value 2*epoch=partial, 2*epoch+1=inclusive
__device__ int    g_epoch = 0;

// Precomputed constants:
// g_c[0] = {k1, k2, k3, e1}   g_c[1] = {e2, e3, a00, a01}
// g_c[2] = {a10, a11, m00, m01}  g_c[3] = {m10, m11, -, -}
__device__ float4 g_c[4];
__device__ float4 g_row4[16];  // (a,b) pairs of row0(A^(j+1)), j=0..31

__device__ __forceinline__ float bsig(float raw, float lo, float hi) {
    return lo + (hi - lo) / (1.0f + expf(-raw));
}

// ---------------------------------------------------------------------------
// Precompute kernel: 1 thread. Folds params, M=A^32, correction table, epoch.
// ---------------------------------------------------------------------------
__global__ void precompute(
    const float* rRi, const float* rRe, const float* rCi, const float* rCe,
    const float* rAi, const float* rAe, const float* rHg)
{
    float Ri = bsig(rRi[0], 1e-4f, 0.2f);
    float Re = bsig(rRe[0], 1e-4f, 0.2f);
    float Ci = bsig(rCi[0], 1e5f,  1e8f);
    float Ce = bsig(rCe[0], 1e5f,  1e8f);
    float Ai = bsig(rAi[0], 0.0f,  0.2f);
    float Ae = bsig(rAe[0], 0.0f,  0.2f);
    float Hg = bsig(rHg[0], 1.0f,  2e4f);
    float dci = 300.0f / Ci;
    float dce = 300.0f / Ce;
    float k1 = dci / Ri, k2 = dci * Ai, k3 = -dci * Hg;   // MODE_COOL
    float e1 = dce / Ri, e2 = dce / Re, e3 = dce * Ae;
    float a00 = 1.0f - k1, a01 = k1;
    float a10 = e1,        a11 = 1.0f - e1 - e2;

    // M = A^32 via 5 squarings
    float m00 = a00, m01 = a01, m10 = a10, m11 = a11;
    for (int i = 0; i < 5; i++) {
        float tr  = m00 + m11;
        float n00 = fmaf(m00, m00, m01 * m10);
        float n11 = fmaf(m11, m11, m01 * m10);
        float n01 = m01 * tr;
        float n10 = m10 * tr;
        m00 = n00; m01 = n01; m10 = n10; m11 = n11;
    }

    g_c[0] = make_float4(k1, k2, k3, e1);
    g_c[1] = make_float4(e2, e3, a00, a01);
    g_c[2] = make_float4(a10, a11, m00, m01);
    g_c[3] = make_float4(m10, m11, 0.f, 0.f);

    // row0(A^(j+1)) pairs, packed 2 per float4
    float al = a00, be = a01;
    for (int j = 0; j < SEG_LEN; j++) {
        float* p = (float*)&g_row4[j >> 1];
        p[(j & 1) * 2 + 0] = al;
        p[(j & 1) * 2 + 1] = be;
        float nal = fmaf(al, a00, be * a10);
        float nbe = fmaf(al, a01, be * a11);
        al = nal; be = nbe;
    }

    g_epoch = g_epoch + 1;   // new epoch invalidates all stale flags
}

__device__ __forceinline__ void flag_release(int* p, int v) {
    asm volatile("st.release.gpu.global.b32 [%0], %1;" :: "l"(p), "r"(v) : "memory");
}
__device__ __forceinline__ int flag_acquire(const int* p) {
    int v;
    asm volatile("ld.acquire.gpu.global.b32 %0, [%1];" : "=r"(v) : "l"(p) : "memory");
    return v;
}

__device__ __forceinline__ void set_comp(float4& v, int k, float x) {
    if      (k == 0) v.x = x;
    else if (k == 1) v.y = x;
    else if (k == 2) v.z = x;
    else             v.w = x;
}

// ---------------------------------------------------------------------------
// Warp-per-(32-building tile, 32-step segment), 2 warps/block. Per-warp
// 2-stage cp.async chunk pipeline (8KB); XOR-swizzled tiles; in-register
// outputs; table-driven correction; float4 transpose + STG.128 flush.
// ---------------------------------------------------------------------------
__global__ void __launch_bounds__(32 * WPB) rc_lookback(
    const float4* __restrict__ in, float* __restrict__ out,
    int B)
{
    __shared__ __align__(16) char sbuf[WPB][2][32 * 8 * 16];

    int w    = threadIdx.x >> 5;
    int lane = threadIdx.x & 31;
    int unit = blockIdx.x * WPB + w;     // monotone in s -> lookback progress
    int s    = unit / NTILES;
    int tl   = unit - s * NTILES;
    int b0   = tl * 32;
    int b    = b0 + lane;

    // broadcast constant loads (L1/L2 hot)
    float4 c0 = __ldg(&g_c[0]);
    float4 c1 = __ldg(&g_c[1]);
    float k1 = c0.x, k2 = c0.y, k3 = c0.z, e1 = c0.w;
    float e2 = c1.x, e3 = c1.y;
    int epoch = __ldg(&g_epoch);
    int fP = epoch * 2, fI = epoch * 2 + 1;

    const char* gbase = (const char*)(in + (size_t)b0 * T_STEPS + s * SEG_LEN);
    int jr = lane & 7;
    int rr = lane >> 3;

    auto issue_chunk = [&](int ch) {
        char* buf = sbuf[w][ch & 1];
        #pragma unroll
        for (int i = 0; i < 8; i++) {
            int r = i * 4 + rr;
            const char* src = gbase + ((size_t)r * T_STEPS + ch * 8 + jr) * 16;
            char* dst = buf + r * 128 + ((jr ^ (r & 7)) * 16);
            __pipeline_memcpy_async(dst, src, 16);
        }
        __pipeline_commit();
    };

    issue_chunk(0);
    issue_chunk(1);

    float4 outs4[8];
    float pin = 0.0f, penv = 0.0f;
    bool first = (s == 0);

    #pragma unroll
    for (int ch = 0; ch < 4; ch++) {
        __pipeline_wait_prior(1);
        __syncwarp();
        const float4* buf = reinterpret_cast<const float4*>(sbuf[w][ch & 1]);
        if (ch == 0 && first) {
            float4 f0 = buf[lane * 8 + (0 ^ (lane & 7))];
            pin  = f0.x;
            penv = 0.5f * (f0.x + f0.y);
        }
        #pragma unroll
        for (int j = 0; j < 8; j++) {
            float4 f = buf[lane * 8 + (j ^ (lane & 7))];   // conflict-free
            float t_out = f.y, hv = f.z, sol = f.w;
            float p    = fmaf(k2, sol, k3 * hv);
            float nin  = fmaf(k1, penv - pin, pin + p);
            float q    = fmaf(e3, sol, penv);
            float nenv = fmaf(e1, pin - penv, fmaf(e2, t_out - penv, q));
            pin = nin; penv = nenv;
            set_comp(outs4[ch * 2 + (j >> 2)], j & 3, nin);
        }
        __syncwarp();
        if (ch + 2 < 4) issue_chunk(ch + 2);
        else            __pipeline_commit();   // uniform group count
    }

    int idx = s * B + b;
    if (first) {
        g_incl[idx] = make_float2(pin, penv);
        flag_release(&g_flag[idx], fI);
    } else {
        g_part[idx] = make_float2(pin, penv);
        flag_release(&g_flag[idx], fP);

        float4 c2 = __ldg(&g_c[2]);
        float4 c3 = __ldg(&g_c[3]);
        float m00 = c2.z, m01 = c2.w, m10 = c3.x, m11 = c3.y;

        // lookback: x_start = d_{s-1} + M d_{s-2} + ... + M^{s-1-i} incl_i
        float xi = 0.0f, xe = 0.0f;
        float p00 = 1.0f, p01 = 0.0f, p10 = 0.0f, p11 = 1.0f;
        for (int i = s - 1; i >= 0; --i) {
            int pidx = i * B + b;
            int f;
            while ((f = flag_acquire(&g_flag[pidx])) < fP) { __nanosleep(40); }
            const float* vp = (f == fI) ? (const float*)&g_incl[pidx]
                                        : (const float*)&g_part[pidx];
            float vx = *(volatile const float*)(vp + 0);
            float vy = *(volatile const float*)(vp + 1);
            xi = fmaf(p00, vx, fmaf(p01, vy, xi));
            xe = fmaf(p10, vx, fmaf(p11, vy, xe));
            if (f == fI) break;
            float q00 = fmaf(p00, m00, p01 * m10), q01 = fmaf(p00, m01, p01 * m11);
            float q10 = fmaf(p10, m00, p11 * m10), q11 = fmaf(p10, m01, p11 * m11);
            p00 = q00; p01 = q01; p10 = q10; p11 = q11;
        }

        // publish inclusive ASAP to unblock successors
        float ix = fmaf(m00, xi, fmaf(m01, xe, pin));
        float ie = fmaf(m10, xi, fmaf(m11, xe, penv));
        g_incl[idx] = make_float2(ix, ie);
        flag_release(&g_flag[idx], fI);

        // table-driven correction: 32 independent FMAs, no serial chain
        #pragma unroll
        for (int jj = 0; jj < 8; jj++) {
            float4 ab0 = __ldg(&g_row4[jj * 2 + 0]);   // j=4jj, 4jj+1
            float4 ab1 = __ldg(&g_row4[jj * 2 + 1]);   // j=4jj+2, 4jj+3
            outs4[jj].x = fmaf(ab0.x, xi, fmaf(ab0.y, xe, outs4[jj].x));
            outs4[jj].y = fmaf(ab0.z, xi, fmaf(ab0.w, xe, outs4[jj].y));
            outs4[jj].z = fmaf(ab1.x, xi, fmaf(ab1.y, xe, outs4[jj].z));
            outs4[jj].w = fmaf(ab1.z, xi, fmaf(ab1.w, xe, outs4[jj].w));
        }
    }

    // float4 XOR-swizzled transpose in this warp's smem, then 8 STG.128
    __syncwarp();
    float4* ot = reinterpret_cast<float4*>(&sbuf[w][0][0]);   // 32x8 float4
    #pragma unroll
    for (int jj = 0; jj < 8; jj++)
        ot[lane * 8 + (jj ^ (lane & 7))] = outs4[jj];          // conflict-free STS.128
    __syncwarp();
    float4* o4 = reinterpret_cast<float4*>(out);
    int cq = lane & 7;            // column quad (t group of 4)
    int rb = lane >> 3;           // row sub-group
    #pragma unroll
    for (int i = 0; i < 8; i++) {
        int r = i * 4 + rb;
        float4 v = ot[r * 8 + (cq ^ (r & 7))];
        __stcs(&o4[(size_t)(b0 + r) * (T_STEPS / 4) + s * 8 + cq], v);
    }
}

// ---------------------------------------------------------------------------
extern "C" void kernel_launch(void* const* d_in, const int* in_sizes, int n_in,
                              void* d_out, int out_size) {
    const float4* in  = (const float4*)d_in[0];
    const float* rRi = (const float*)d_in[1];
    const float* rRe = (const float*)d_in[2];
    const float* rCi = (const float*)d_in[3];
    const float* rCe = (const float*)d_in[4];
    const float* rAi = (const float*)d_in[5];
    const float* rAe = (const float*)d_in[6];
    const float* rHg = (const float*)d_in[7];
    float* out = (float*)d_out;

    int B = in_sizes[0] / (T_STEPS * 4);   // 16384

    precompute<<<1, 1>>>(rRi, rRe, rCi, rCe, rAi, rAe, rHg);

    int units  = NTILES * NSEG;            // 23040
    int blocks = units / WPB;              // 11520
    rc_lookback<<<blocks, 32 * WPB>>>(in, out, B);
}

// round 12
// speedup vs baseline: 1.1607x; 1.0205x over previous
#include <cuda_runtime.h>
#include <cuda_pipeline.h>
#include <math.h>

#define T_STEPS 1440
#define SEG_LEN 32
#define NSEG    45           // 1440 / 32
#define B_MAX   16384
#define NTILES  (B_MAX / 32) // 512
#define WPB     2            // warps per block

// Decoupled-lookback state; flags memset to 0 per launch (graph memset node).
__device__ float2 g_part[NSEG * B_MAX];
__device__ float2 g_incl[NSEG * B_MAX];
__device__ int    g_flag[NSEG * B_MAX];   // 0=empty, 1=partial, 2=inclusive

__device__ __forceinline__ float bsig(float raw, float lo, float hi) {
    return lo + (hi - lo) / (1.0f + expf(-raw));
}

__device__ __forceinline__ void flag_release(int* p, int v) {
    asm volatile("st.release.gpu.global.b32 [%0], %1;" :: "l"(p), "r"(v) : "memory");
}
__device__ __forceinline__ int flag_acquire(const int* p) {
    int v;
    asm volatile("ld.acquire.gpu.global.b32 %0, [%1];" : "=r"(v) : "l"(p) : "memory");
    return v;
}

__device__ __forceinline__ void set_comp(float4& v, int k, float x) {
    if      (k == 0) v.x = x;
    else if (k == 1) v.y = x;
    else if (k == 2) v.z = x;
    else             v.w = x;
}

// ---------------------------------------------------------------------------
// Warp-per-(32-building tile, 32-step segment), 2 warps/block. Per-warp
// 2-stage cp.async chunk pipeline (8KB); XOR-swizzled tiles; in-register
// outputs; smem-table correction (built in-block by warp 0 via per-lane
// binary powering); float4 transpose + STG.128 flush.
// ---------------------------------------------------------------------------
__global__ void __launch_bounds__(32 * WPB, 13) rc_lookback(
    const float4* __restrict__ in, float* __restrict__ out,
    const float* __restrict__ rRi, const float* __restrict__ rRe,
    const float* __restrict__ rCi, const float* __restrict__ rCe,
    const float* __restrict__ rAi, const float* __restrict__ rAe,
    const float* __restrict__ rHg, int B)
{
    __shared__ __align__(16) char sbuf[WPB][2][32 * 8 * 16];
    __shared__ float2 s_row[SEG_LEN];     // row0(A^(j+1)), j=0..31
    __shared__ float4 s_M;                // A^32 (m00,m01,m10,m11)

    int w    = threadIdx.x >> 5;
    int lane = threadIdx.x & 31;
    int unit = blockIdx.x * WPB + w;      // monotone in s -> lookback progress
    int s    = unit / NTILES;
    int tl   = unit - s * NTILES;
    int b0   = tl * 32;
    int b    = b0 + lane;

    // folded coefficients (per-thread; 7 MUFU chains, independent)
    float Ri = bsig(rRi[0], 1e-4f, 0.2f);
    float Re = bsig(rRe[0], 1e-4f, 0.2f);
    float Ci = bsig(rCi[0], 1e5f,  1e8f);
    float Ce = bsig(rCe[0], 1e5f,  1e8f);
    float Ai = bsig(rAi[0], 0.0f,  0.2f);
    float Ae = bsig(rAe[0], 0.0f,  0.2f);
    float Hg = bsig(rHg[0], 1.0f,  2e4f);
    float dci = 300.0f / Ci, dce = 300.0f / Ce;
    float k1 = dci / Ri, k2 = dci * Ai, k3 = -dci * Hg;   // MODE_COOL
    float e1 = dce / Ri, e2 = dce / Re, e3 = dce * Ae;
    float a00 = 1.0f - k1, a01 = k1;
    float a10 = e1,        a11 = 1.0f - e1 - e2;

    const char* gbase = (const char*)(in + (size_t)b0 * T_STEPS + s * SEG_LEN);
    int jr = lane & 7;
    int rr = lane >> 3;

    auto issue_chunk = [&](int ch) {
        char* buf = sbuf[w][ch & 1];
        #pragma unroll
        for (int i = 0; i < 8; i++) {
            int r = i * 4 + rr;
            const char* src = gbase + ((size_t)r * T_STEPS + ch * 8 + jr) * 16;
            char* dst = buf + r * 128 + ((jr ^ (r & 7)) * 16);
            __pipeline_memcpy_async(dst, src, 16);
        }
        __pipeline_commit();
    };

    // get loads moving first; table build overlaps them
    issue_chunk(0);
    issue_chunk(1);

    // warp 0: lane j computes A^(j+1) by binary powering (powers commute)
    if (w == 0) {
        int e = lane + 1;
        float p00 = 1.f, p01 = 0.f, p10 = 0.f, p11 = 1.f;
        float s00 = a00, s01 = a01, s10 = a10, s11 = a11;  // S = A^(2^bit)
        #pragma unroll
        for (int bit = 0; bit < 6; bit++) {
            if ((e >> bit) & 1) {
                float t00 = fmaf(p00, s00, p01 * s10), t01 = fmaf(p00, s01, p01 * s11);
                float t10 = fmaf(p10, s00, p11 * s10), t11 = fmaf(p10, s01, p11 * s11);
                p00 = t00; p01 = t01; p10 = t10; p11 = t11;
            }
            float tr  = s00 + s11;
            float n00 = fmaf(s00, s00, s01 * s10);
            float n11 = fmaf(s11, s11, s01 * s10);
            float n01 = s01 * tr, n10 = s10 * tr;
            s00 = n00; s01 = n01; s10 = n10; s11 = n11;
        }
        s_row[lane] = make_float2(p00, p01);
        if (lane == 31) s_M = make_float4(p00, p01, p10, p11);  // A^32
    }
    __syncthreads();

    float4 outs4[8];
    float pin = 0.0f, penv = 0.0f;
    bool first = (s == 0);

    #pragma unroll
    for (int ch = 0; ch < 4; ch++) {
        __pipeline_wait_prior(1);
        __syncwarp();
        const float4* buf = reinterpret_cast<const float4*>(sbuf[w][ch & 1]);
        if (ch == 0 && first) {
            float4 f0 = buf[lane * 8 + (0 ^ (lane & 7))];
            pin  = f0.x;
            penv = 0.5f * (f0.x + f0.y);
        }
        #pragma unroll
        for (int j = 0; j < 8; j++) {
            float4 f = buf[lane * 8 + (j ^ (lane & 7))];   // conflict-free
            float t_out = f.y, hv = f.z, sol = f.w;
            float p    = fmaf(k2, sol, k3 * hv);
            float nin  = fmaf(k1, penv - pin, pin + p);
            float q    = fmaf(e3, sol, penv);
            float nenv = fmaf(e1, pin - penv, fmaf(e2, t_out - penv, q));
            pin = nin; penv = nenv;
            set_comp(outs4[ch * 2 + (j >> 2)], j & 3, nin);
        }
        __syncwarp();
        if (ch + 2 < 4) issue_chunk(ch + 2);
        else            __pipeline_commit();   // uniform group count
    }

    int idx = s * B + b;
    if (first) {
        g_incl[idx] = make_float2(pin, penv);
        flag_release(&g_flag[idx], 2);
    } else {
        g_part[idx] = make_float2(pin, penv);
        flag_release(&g_flag[idx], 1);

        float4 M = s_M;
        float m00 = M.x, m01 = M.y, m10 = M.z, m11 = M.w;

        // lookback: x_start = d_{s-1} + M d_{s-2} + ... + M^{s-1-i} incl_i
        float xi = 0.0f, xe = 0.0f;
        float p00 = 1.0f, p01 = 0.0f, p10 = 0.0f, p11 = 1.0f;
        for (int i = s - 1; i >= 0; --i) {
            int pidx = i * B + b;
            int f;
            while ((f = flag_acquire(&g_flag[pidx])) == 0) { __nanosleep(40); }
            const float* vp = (f == 2) ? (const float*)&g_incl[pidx]
                                       : (const float*)&g_part[pidx];
            float vx = *(volatile const float*)(vp + 0);
            float vy = *(volatile const float*)(vp + 1);
            xi = fmaf(p00, vx, fmaf(p01, vy, xi));
            xe = fmaf(p10, vx, fmaf(p11, vy, xe));
            if (f == 2) break;
            float q00 = fmaf(p00, m00, p01 * m10), q01 = fmaf(p00, m01, p01 * m11);
            float q10 = fmaf(p10, m00, p11 * m10), q11 = fmaf(p10, m01, p11 * m11);
            p00 = q00; p01 = q01; p10 = q10; p11 = q11;
        }

        // publish inclusive ASAP to unblock successors
        float ix = fmaf(m00, xi, fmaf(m01, xe, pin));
        float ie = fmaf(m10, xi, fmaf(m11, xe, penv));
        g_incl[idx] = make_float2(ix, ie);
        flag_release(&g_flag[idx], 2);

        // table-driven correction: 32 independent FMAs (LDS broadcasts)
        #pragma unroll
        for (int jj = 0; jj < 8; jj++) {
            float2 r0 = s_row[jj * 4 + 0];
            float2 r1 = s_row[jj * 4 + 1];
            float2 r2 = s_row[jj * 4 + 2];
            float2 r3 = s_row[jj * 4 + 3];
            outs4[jj].x = fmaf(r0.x, xi, fmaf(r0.y, xe, outs4[jj].x));
            outs4[jj].y = fmaf(r1.x, xi, fmaf(r1.y, xe, outs4[jj].y));
            outs4[jj].z = fmaf(r2.x, xi, fmaf(r2.y, xe, outs4[jj].z));
            outs4[jj].w = fmaf(r3.x, xi, fmaf(r3.y, xe, outs4[jj].w));
        }
    }

    // float4 XOR-swizzled transpose in this warp's smem, then 8 STG.128
    __syncwarp();
    float4* ot = reinterpret_cast<float4*>(&sbuf[w][0][0]);   // 32x8 float4
    #pragma unroll
    for (int jj = 0; jj < 8; jj++)
        ot[lane * 8 + (jj ^ (lane & 7))] = outs4[jj];          // conflict-free STS.128
    __syncwarp();
    float4* o4 = reinterpret_cast<float4*>(out);
    int cq = lane & 7;            // column quad (t group of 4)
    int rb = lane >> 3;           // row sub-group
    #pragma unroll
    for (int i = 0; i < 8; i++) {
        int r = i * 4 + rb;
        float4 v = ot[r * 8 + (cq ^ (r & 7))];
        __stcs(&o4[(size_t)(b0 + r) * (T_STEPS / 4) + s * 8 + cq], v);
    }
}

// ---------------------------------------------------------------------------
extern "C" void kernel_launch(void* const* d_in, const int* in_sizes, int n_in,
                              void* d_out, int out_size) {
    const float4* in  = (const float4*)d_in[0];
    const float* rRi = (const float*)d_in[1];
    const float* rRe = (const float*)d_in[2];
    const float* rCi = (const float*)d_in[3];
    const float* rCe = (const float*)d_in[4];
    const float* rAi = (const float*)d_in[5];
    const float* rAe = (const float*)d_in[6];
    const float* rHg = (const float*)d_in[7];
    float* out = (float*)d_out;

    int B = in_sizes[0] / (T_STEPS * 4);   // 16384

    // reset lookback flags (graph-capturable memset node; no allocation)
    void* flag_ptr = nullptr;
    cudaGetSymbolAddress(&flag_ptr, g_flag);
    cudaMemsetAsync(flag_ptr, 0, (size_t)NSEG * B_MAX * sizeof(int), 0);

    int units  = NTILES * NSEG;            // 23040
    int blocks = units / WPB;              // 11520
    rc_lookback<<<blocks, 32 * WPB>>>(in, out, rRi, rRe, rCi, rCe, rAi, rAe, rHg, B);
}